// round 4
// baseline (speedup 1.0000x reference)
#include <cuda_runtime.h>
#include <cuda_bf16.h>
#include <cstdint>
#include <cstddef>

// ---------------------------------------------------------------------------
// Attention_87428354277788 — R4: split-bf16 HMMA GEMM v2 (128x256 CTA tile,
// 64x64 warp tile, 3-stage cp.async) + f32x2-packed flash attention.
// ---------------------------------------------------------------------------

typedef unsigned long long u64;
typedef __nv_bfloat16 bf16;

__device__ float g_qkv[75497472];      // [32768, 2304]
__device__ float g_attn[25165824];     // [32768, 768]
__device__ float g_bias[786432];       // [12, 256, 256]
__device__ bf16  g_ah[25165824];       // A hi (x, then attn) [32768,768]
__device__ bf16  g_al[25165824];       // A lo
__device__ bf16  g_bqh[1769472];       // WqkvT hi [2304,768]
__device__ bf16  g_bql[1769472];
__device__ bf16  g_boh[589824];        // WoutT hi [768,768]
__device__ bf16  g_bol[589824];

// ---------------------------------------------------------------------------
__device__ __forceinline__ uint32_t smem_u32(const void* p) {
    uint32_t a;
    asm("{ .reg .u64 t; cvta.to.shared.u64 t, %1; cvt.u32.u64 %0, t; }"
        : "=r"(a) : "l"(p));
    return a;
}
__device__ __forceinline__ void cp16(uint32_t s, const void* g) {
    asm volatile("cp.async.cg.shared.global [%0], [%1], 16;" :: "r"(s), "l"(g));
}
#define CP_COMMIT() asm volatile("cp.async.commit_group;" ::: "memory")
#define CP_WAIT1()  asm volatile("cp.async.wait_group 1;" ::: "memory")

__device__ __forceinline__ void ldsm4(uint32_t* r, uint32_t addr) {
    asm volatile("ldmatrix.sync.aligned.m8n8.x4.shared.b16 {%0,%1,%2,%3}, [%4];"
        : "=r"(r[0]), "=r"(r[1]), "=r"(r[2]), "=r"(r[3]) : "r"(addr));
}
__device__ __forceinline__ void mma_bf16(float* c, const uint32_t* a,
                                         const uint32_t* b) {
    asm volatile(
        "mma.sync.aligned.m16n8k16.row.col.f32.bf16.bf16.f32 "
        "{%0,%1,%2,%3}, {%4,%5,%6,%7}, {%8,%9}, {%0,%1,%2,%3};"
        : "+f"(c[0]), "+f"(c[1]), "+f"(c[2]), "+f"(c[3])
        : "r"(a[0]), "r"(a[1]), "r"(a[2]), "r"(a[3]), "r"(b[0]), "r"(b[1]));
}

// f32x2 packed helpers
__device__ __forceinline__ u64 pack2(float x, float y) {
    u64 r; asm("mov.b64 %0, {%1, %2};" : "=l"(r) : "f"(x), "f"(y)); return r;
}
__device__ __forceinline__ u64 fma2(u64 a, u64 b, u64 c) {
    u64 d; asm("fma.rn.f32x2 %0, %1, %2, %3;" : "=l"(d) : "l"(a), "l"(b), "l"(c));
    return d;
}
__device__ __forceinline__ u64 mul2(u64 a, u64 b) {
    u64 d; asm("mul.rn.f32x2 %0, %1, %2;" : "=l"(d) : "l"(a), "l"(b));
    return d;
}
__device__ __forceinline__ float2 unpack2(u64 v) {
    float2 f; asm("mov.b64 {%0, %1}, %2;" : "=f"(f.x), "=f"(f.y) : "l"(v)); return f;
}

// ---------------------------------------------------------------------------
__global__ void split_kernel(const float* __restrict__ in,
                             bf16* __restrict__ hi, bf16* __restrict__ lo,
                             int n4)
{
    int i = blockIdx.x * 256 + threadIdx.x;
    if (i >= n4) return;
    float4 v = ((const float4*)in)[i];
    bf16 h0 = __float2bfloat16_rn(v.x);
    bf16 h1 = __float2bfloat16_rn(v.y);
    bf16 h2 = __float2bfloat16_rn(v.z);
    bf16 h3 = __float2bfloat16_rn(v.w);
    bf16 l0 = __float2bfloat16_rn(v.x - __bfloat162float(h0));
    bf16 l1 = __float2bfloat16_rn(v.y - __bfloat162float(h1));
    bf16 l2 = __float2bfloat16_rn(v.z - __bfloat162float(h2));
    bf16 l3 = __float2bfloat16_rn(v.w - __bfloat162float(h3));
    ((ushort4*)hi)[i] = make_ushort4(__bfloat16_as_ushort(h0), __bfloat16_as_ushort(h1),
                                     __bfloat16_as_ushort(h2), __bfloat16_as_ushort(h3));
    ((ushort4*)lo)[i] = make_ushort4(__bfloat16_as_ushort(l0), __bfloat16_as_ushort(l1),
                                     __bfloat16_as_ushort(l2), __bfloat16_as_ushort(l3));
}

__global__ void split_transpose_kernel(const float* __restrict__ in,
                                       bf16* __restrict__ outh,
                                       bf16* __restrict__ outl, int R, int C)
{
    __shared__ float t[32][33];
    int c0 = blockIdx.x * 32, r0 = blockIdx.y * 32;
#pragma unroll
    for (int i = threadIdx.y; i < 32; i += 8)
        t[i][threadIdx.x] = in[(size_t)(r0 + i) * C + c0 + threadIdx.x];
    __syncthreads();
#pragma unroll
    for (int i = threadIdx.y; i < 32; i += 8) {
        float v = t[threadIdx.x][i];
        bf16 h = __float2bfloat16_rn(v);
        bf16 l = __float2bfloat16_rn(v - __bfloat162float(h));
        size_t o = (size_t)(c0 + i) * R + r0 + threadIdx.x;
        outh[o] = h; outl[o] = l;
    }
}

__global__ void bias_gather_kernel(const int* __restrict__ ids,
                                   const float* __restrict__ table,
                                   float* __restrict__ biasmat)
{
    int pos = blockIdx.x * 256 + threadIdx.x;
    int id = ids[pos];
#pragma unroll
    for (int h = 0; h < 12; h++)
        biasmat[h * 65536 + pos] = table[id * 12 + h];
}

// ---------------------------------------------------------------------------
// GEMM v2: C[M,N] = A@BT^T + bias, split-bf16 (3 MMA terms).
// CTA 128(M) x 256(N), 8 warps 2(M)x4(N), warp tile 64x64, BK=32,
// 3-stage cp.async pipeline.
// ---------------------------------------------------------------------------
#define RSB   80
#define PA    10240           // A part: 128 rows * 80B
#define PB    20480           // B part: 256 rows * 80B
#define STG   61440           // Ah|Al|Bh|Bl
#define GSM   (3 * STG)       // 180 KB

__global__ __launch_bounds__(256, 1) void hgemm_kernel(
    const bf16* __restrict__ Ah, const bf16* __restrict__ Al,
    const bf16* __restrict__ Bh, const bf16* __restrict__ Bl,
    const float* __restrict__ bias, float* __restrict__ C,
    int M, int N, int K)
{
    extern __shared__ char smraw[];
    const uint32_t sbase = smem_u32(smraw);
    const int tid = threadIdx.x;
    const int lane = tid & 31;
    const int wid = tid >> 5;
    const int warp_m = wid >> 2;     // 0..1
    const int warp_n = wid & 3;      // 0..3
    const int m0 = blockIdx.y * 128;
    const int n0 = blockIdx.x * 256;

    const bf16* Ah_g = Ah + (size_t)m0 * K;
    const bf16* Al_g = Al + (size_t)m0 * K;
    const bf16* Bh_g = Bh + (size_t)n0 * K;
    const bf16* Bl_g = Bl + (size_t)n0 * K;

    const uint32_t a_lane = (uint32_t)((lane & 15) * RSB + (lane >> 4) * 16
                          + warp_m * 64 * RSB);
    const uint32_t b_lane = (uint32_t)(((lane & 7) + (lane >> 4) * 8) * RSB
                          + ((lane >> 3) & 1) * 16 + warp_n * 64 * RSB);

    float acc[4][8][4];
#pragma unroll
    for (int i = 0; i < 4; i++)
#pragma unroll
        for (int j = 0; j < 8; j++)
#pragma unroll
            for (int q = 0; q < 4; q++) acc[i][j][q] = 0.f;

    const int nch = K >> 5;          // 24
    const int r_ = tid >> 2, seg_ = tid & 3;

#define LOAD_STAGE(ch) do {                                                    \
        const int k0_ = (ch) << 5;                                             \
        const uint32_t sst = sbase + (uint32_t)((ch) % 3) * STG;               \
        _Pragma("unroll")                                                      \
        for (int it = 0; it < 2; it++) {                                       \
            int row = r_ + it * 64;                                            \
            cp16(sst + row * RSB + seg_ * 16,                                  \
                 Ah_g + (size_t)row * K + k0_ + seg_ * 8);                     \
            cp16(sst + PA + row * RSB + seg_ * 16,                             \
                 Al_g + (size_t)row * K + k0_ + seg_ * 8);                     \
        }                                                                      \
        _Pragma("unroll")                                                      \
        for (int it = 0; it < 4; it++) {                                       \
            int row = r_ + it * 64;                                            \
            cp16(sst + 2 * PA + row * RSB + seg_ * 16,                         \
                 Bh_g + (size_t)row * K + k0_ + seg_ * 8);                     \
            cp16(sst + 2 * PA + PB + row * RSB + seg_ * 16,                    \
                 Bl_g + (size_t)row * K + k0_ + seg_ * 8);                     \
        }                                                                      \
        CP_COMMIT();                                                           \
    } while (0)

    LOAD_STAGE(0);
    LOAD_STAGE(1);

    for (int ch = 0; ch < nch; ch++) {
        CP_WAIT1();
        __syncthreads();
        if (ch + 2 < nch) LOAD_STAGE(ch + 2);

        const uint32_t sbuf = sbase + (uint32_t)(ch % 3) * STG;
        const uint32_t sAh = sbuf + a_lane;
        const uint32_t sAl = sbuf + PA + a_lane;
        const uint32_t sBh = sbuf + 2 * PA + b_lane;
        const uint32_t sBl = sbuf + 2 * PA + PB + b_lane;

#pragma unroll
        for (int ko = 0; ko < 2; ko++) {
            const uint32_t kb = ko * 32;
            uint32_t bh[4][4], bl[4][4];
#pragma unroll
            for (int nt16 = 0; nt16 < 4; nt16++) {
                ldsm4(bh[nt16], sBh + nt16 * (16 * RSB) + kb);
                ldsm4(bl[nt16], sBl + nt16 * (16 * RSB) + kb);
            }
#pragma unroll
            for (int mt = 0; mt < 4; mt++) {
                uint32_t ah[4], al[4];
                ldsm4(ah, sAh + mt * (16 * RSB) + kb);
                ldsm4(al, sAl + mt * (16 * RSB) + kb);
#pragma unroll
                for (int nt16 = 0; nt16 < 4; nt16++) {
                    mma_bf16(acc[mt][2 * nt16],     ah, &bh[nt16][0]);
                    mma_bf16(acc[mt][2 * nt16 + 1], ah, &bh[nt16][2]);
                    mma_bf16(acc[mt][2 * nt16],     ah, &bl[nt16][0]);
                    mma_bf16(acc[mt][2 * nt16 + 1], ah, &bl[nt16][2]);
                    mma_bf16(acc[mt][2 * nt16],     al, &bh[nt16][0]);
                    mma_bf16(acc[mt][2 * nt16 + 1], al, &bh[nt16][2]);
                }
            }
        }
    }
#undef LOAD_STAGE

    // epilogue
    const int quad = lane >> 2, tq = lane & 3;
#pragma unroll
    for (int mt = 0; mt < 4; mt++) {
        const int r = m0 + warp_m * 64 + mt * 16 + quad;
#pragma unroll
        for (int nt = 0; nt < 8; nt++) {
            const int c = n0 + warp_n * 64 + nt * 8 + tq * 2;
            const float b0 = bias[c], b1 = bias[c + 1];
            float* cp = C + (size_t)r * N + c;
            *(float2*)cp = make_float2(acc[mt][nt][0] + b0, acc[mt][nt][1] + b1);
            *(float2*)(cp + 8 * (size_t)N) =
                make_float2(acc[mt][nt][2] + b0, acc[mt][nt][3] + b1);
        }
    }
}

// ---------------------------------------------------------------------------
// Fused attention — f32x2-packed QK and PV loops.
// ---------------------------------------------------------------------------
__global__ __launch_bounds__(256) void attn_kernel(
    const float* __restrict__ qkv, const float* __restrict__ biasmat,
    float* __restrict__ attn_out)
{
    extern __shared__ float sm[];
    const int P = 68;
    float* Qs = sm;
    float* Ks = sm + 64 * P;
    float* Vs = sm + 2 * 64 * P;
    float* Ss = sm + 3 * 64 * P;

    const int qt = blockIdx.x, h = blockIdx.y, b = blockIdx.z;
    const int tid = threadIdx.x;
    const int tyy = tid >> 4, txx = tid & 15;
    const int r0 = tyy << 2;
    const int q0 = qt << 6;

    const size_t RS = 2304;
    const float* qg  = qkv + (size_t)(b * 256 + q0) * RS + h * 64;
    const float* kg0 = qkv + (size_t)(b * 256) * RS + 768 + h * 64;
    const float* vg0 = kg0 + 768;

#pragma unroll
    for (int l = 0; l < 4; l++) {
        int f = tid + (l << 8);
        int i = f >> 4, dd = (f & 15) << 2;
        *(float4*)(Qs + i * P + dd) = *(const float4*)(qg + (size_t)i * RS + dd);
    }

    float m[4], lsum[4];
    u64 o2[4][2];
#pragma unroll
    for (int i = 0; i < 4; i++) {
        m[i] = -1e30f; lsum[i] = 0.f;
        o2[i][0] = 0ULL; o2[i][1] = 0ULL;
    }

    const float* bb = biasmat + (size_t)h * 65536 + (size_t)q0 * 256;

    for (int kt = 0; kt < 4; kt++) {
        __syncthreads();
        const float* kg = kg0 + (size_t)(kt * 64) * RS;
        const float* vg = vg0 + (size_t)(kt * 64) * RS;
#pragma unroll
        for (int l = 0; l < 4; l++) {
            int f = tid + (l << 8);
            int i = f >> 4, dd = (f & 15) << 2;
            *(float4*)(Ks + i * P + dd) = *(const float4*)(kg + (size_t)i * RS + dd);
            *(float4*)(Vs + i * P + dd) = *(const float4*)(vg + (size_t)i * RS + dd);
        }
        __syncthreads();

        // --- scores (packed f32x2 over d) ---
        u64 s2[4][4];
#pragma unroll
        for (int i = 0; i < 4; i++)
#pragma unroll
            for (int j = 0; j < 4; j++) s2[i][j] = 0ULL;

#pragma unroll
        for (int d4 = 0; d4 < 16; d4++) {
            ulonglong2 a[4], kv[4];
#pragma unroll
            for (int i = 0; i < 4; i++)
                a[i] = *(const ulonglong2*)(Qs + (r0 + i) * P + (d4 << 2));
#pragma unroll
            for (int j = 0; j < 4; j++)
                kv[j] = *(const ulonglong2*)(Ks + (txx + (j << 4)) * P + (d4 << 2));
#pragma unroll
            for (int i = 0; i < 4; i++)
#pragma unroll
                for (int j = 0; j < 4; j++)
                    s2[i][j] = fma2(a[i].y, kv[j].y, fma2(a[i].x, kv[j].x, s2[i][j]));
        }

        float s[4][4];
#pragma unroll
        for (int i = 0; i < 4; i++)
#pragma unroll
            for (int j = 0; j < 4; j++) {
                float2 v = unpack2(s2[i][j]);
                s[i][j] = v.x + v.y;
            }

        // --- bias + online softmax ---
#pragma unroll
        for (int i = 0; i < 4; i++) {
            float tm = -1e30f;
#pragma unroll
            for (int j = 0; j < 4; j++) {
                float bv = bb[(r0 + i) * 256 + kt * 64 + txx + (j << 4)];
                s[i][j] = fmaf(s[i][j], 0.125f, bv);
                tm = fmaxf(tm, s[i][j]);
            }
            tm = fmaxf(tm, __shfl_xor_sync(0xffffffffu, tm, 1));
            tm = fmaxf(tm, __shfl_xor_sync(0xffffffffu, tm, 2));
            tm = fmaxf(tm, __shfl_xor_sync(0xffffffffu, tm, 4));
            tm = fmaxf(tm, __shfl_xor_sync(0xffffffffu, tm, 8));
            float mn = fmaxf(m[i], tm);
            float corr = __expf(m[i] - mn);
            m[i] = mn;
            float ps = 0.f;
#pragma unroll
            for (int j = 0; j < 4; j++) {
                s[i][j] = __expf(s[i][j] - mn);
                ps += s[i][j];
            }
            ps += __shfl_xor_sync(0xffffffffu, ps, 1);
            ps += __shfl_xor_sync(0xffffffffu, ps, 2);
            ps += __shfl_xor_sync(0xffffffffu, ps, 4);
            ps += __shfl_xor_sync(0xffffffffu, ps, 8);
            lsum[i] = lsum[i] * corr + ps;
            u64 c2 = pack2(corr, corr);
            o2[i][0] = mul2(o2[i][0], c2);
            o2[i][1] = mul2(o2[i][1], c2);
        }

        // --- stage P^T to smem ---
#pragma unroll
        for (int j = 0; j < 4; j++)
#pragma unroll
            for (int i = 0; i < 4; i++)
                Ss[(txx + (j << 4)) * P + r0 + i] = s[i][j];
        __syncthreads();

        // --- PV (packed over output cols) ---
#pragma unroll 8
        for (int k = 0; k < 64; k++) {
            float4 pv = *(const float4*)(Ss + k * P + r0);
            ulonglong2 vv = *(const ulonglong2*)(Vs + k * P + (txx << 2));
            u64 p;
            p = pack2(pv.x, pv.x);
            o2[0][0] = fma2(p, vv.x, o2[0][0]); o2[0][1] = fma2(p, vv.y, o2[0][1]);
            p = pack2(pv.y, pv.y);
            o2[1][0] = fma2(p, vv.x, o2[1][0]); o2[1][1] = fma2(p, vv.y, o2[1][1]);
            p = pack2(pv.z, pv.z);
            o2[2][0] = fma2(p, vv.x, o2[2][0]); o2[2][1] = fma2(p, vv.y, o2[2][1]);
            p = pack2(pv.w, pv.w);
            o2[3][0] = fma2(p, vv.x, o2[3][0]); o2[3][1] = fma2(p, vv.y, o2[3][1]);
        }
    }

    float* og = attn_out + (size_t)(b * 256 + q0) * 768 + h * 64 + (txx << 2);
#pragma unroll
    for (int i = 0; i < 4; i++) {
        float inv = 1.0f / lsum[i];
        float2 v0 = unpack2(o2[i][0]);
        float2 v1 = unpack2(o2[i][1]);
        float4 w = make_float4(v0.x * inv, v0.y * inv, v1.x * inv, v1.y * inv);
        *(float4*)(og + (size_t)(r0 + i) * 768) = w;
    }
}

// ---------------------------------------------------------------------------
extern "C" void kernel_launch(void* const* d_in, const int* in_sizes, int n_in,
                              void* d_out, int out_size)
{
    const float* x     = (const float*)d_in[0];
    const float* Wqkv  = (const float*)d_in[1];
    const float* bqkv  = (const float*)d_in[2];
    const float* Wout  = (const float*)d_in[3];
    const float* bout  = (const float*)d_in[4];
    const float* table = (const float*)d_in[5];
    const int*   ids   = (const int*)d_in[6];
    float* out = (float*)d_out;

    float *qkv, *attn, *bias;
    bf16 *ah, *al, *bqh, *bql, *boh, *bol;
    cudaGetSymbolAddress((void**)&qkv,  g_qkv);
    cudaGetSymbolAddress((void**)&attn, g_attn);
    cudaGetSymbolAddress((void**)&bias, g_bias);
    cudaGetSymbolAddress((void**)&ah,   g_ah);
    cudaGetSymbolAddress((void**)&al,   g_al);
    cudaGetSymbolAddress((void**)&bqh,  g_bqh);
    cudaGetSymbolAddress((void**)&bql,  g_bql);
    cudaGetSymbolAddress((void**)&boh,  g_boh);
    cudaGetSymbolAddress((void**)&bol,  g_bol);

    const int ATTN_SMEM = 4 * 64 * 68 * 4;
    cudaFuncSetAttribute(attn_kernel,
                         cudaFuncAttributeMaxDynamicSharedMemorySize, ATTN_SMEM);
    cudaFuncSetAttribute(hgemm_kernel,
                         cudaFuncAttributeMaxDynamicSharedMemorySize, GSM);

    split_transpose_kernel<<<dim3(2304 / 32, 768 / 32), dim3(32, 8)>>>(
        Wqkv, bqh, bql, 768, 2304);
    split_transpose_kernel<<<dim3(768 / 32, 768 / 32), dim3(32, 8)>>>(
        Wout, boh, bol, 768, 768);
    bias_gather_kernel<<<256, 256>>>(ids, table, bias);
    split_kernel<<<25165824 / 4 / 256, 256>>>(x, ah, al, 25165824 / 4);

    hgemm_kernel<<<dim3(2304 / 256, 32768 / 128), 256, GSM>>>(
        ah, al, bqh, bql, bqkv, qkv, 32768, 2304, 768);

    attn_kernel<<<dim3(4, 12, 128), 256, ATTN_SMEM>>>(qkv, bias, attn);

    split_kernel<<<25165824 / 4 / 256, 256>>>(attn, ah, al, 25165824 / 4);

    hgemm_kernel<<<dim3(768 / 256, 32768 / 128), 256, GSM>>>(
        ah, al, boh, bol, bout, out, 32768, 768, 768);
}

// round 5
// speedup vs baseline: 1.3002x; 1.3002x over previous
#include <cuda_runtime.h>
#include <cuda_fp16.h>
#include <cstdint>
#include <cstddef>

// ---------------------------------------------------------------------------
// Attention_87428354277788 — R5: 2-term split-fp16 HMMA GEMMs (Ah·Bh + Al·Bh,
// u_fp16 = 2^-11 -> rel_err ~3e-4), 128x128 CTA tile @ 2 CTA/SM, 3-stage
// cp.async; f32x2-packed flash attention.
// ---------------------------------------------------------------------------

typedef unsigned long long u64;
typedef __half fp16;

__device__ float g_qkv[75497472];      // [32768, 2304]
__device__ float g_attn[25165824];     // [32768, 768]
__device__ float g_bias[786432];       // [12, 256, 256]
__device__ fp16  g_ah[25165824];       // A hi (x, then attn) [32768,768]
__device__ fp16  g_al[25165824];       // A lo
__device__ fp16  g_bqh[1769472];       // WqkvT hi [2304,768]
__device__ fp16  g_bql[1769472];       // WqkvT lo
__device__ fp16  g_boh[589824];        // WoutT hi [768,768]
__device__ fp16  g_bol[589824];        // WoutT lo

// ---------------------------------------------------------------------------
__device__ __forceinline__ uint32_t smem_u32(const void* p) {
    uint32_t a;
    asm("{ .reg .u64 t; cvta.to.shared.u64 t, %1; cvt.u32.u64 %0, t; }"
        : "=r"(a) : "l"(p));
    return a;
}
__device__ __forceinline__ void cp16(uint32_t s, const void* g) {
    asm volatile("cp.async.cg.shared.global [%0], [%1], 16;" :: "r"(s), "l"(g));
}
#define CP_COMMIT() asm volatile("cp.async.commit_group;" ::: "memory")
#define CP_WAIT1()  asm volatile("cp.async.wait_group 1;" ::: "memory")

__device__ __forceinline__ void ldsm4(uint32_t* r, uint32_t addr) {
    asm volatile("ldmatrix.sync.aligned.m8n8.x4.shared.b16 {%0,%1,%2,%3}, [%4];"
        : "=r"(r[0]), "=r"(r[1]), "=r"(r[2]), "=r"(r[3]) : "r"(addr));
}
__device__ __forceinline__ void mma_fp16(float* c, const uint32_t* a,
                                         const uint32_t* b) {
    asm volatile(
        "mma.sync.aligned.m16n8k16.row.col.f32.f16.f16.f32 "
        "{%0,%1,%2,%3}, {%4,%5,%6,%7}, {%8,%9}, {%0,%1,%2,%3};"
        : "+f"(c[0]), "+f"(c[1]), "+f"(c[2]), "+f"(c[3])
        : "r"(a[0]), "r"(a[1]), "r"(a[2]), "r"(a[3]), "r"(b[0]), "r"(b[1]));
}

// f32x2 packed helpers
__device__ __forceinline__ u64 pack2(float x, float y) {
    u64 r; asm("mov.b64 %0, {%1, %2};" : "=l"(r) : "f"(x), "f"(y)); return r;
}
__device__ __forceinline__ u64 fma2(u64 a, u64 b, u64 c) {
    u64 d; asm("fma.rn.f32x2 %0, %1, %2, %3;" : "=l"(d) : "l"(a), "l"(b), "l"(c));
    return d;
}
__device__ __forceinline__ u64 mul2(u64 a, u64 b) {
    u64 d; asm("mul.rn.f32x2 %0, %1, %2;" : "=l"(d) : "l"(a), "l"(b));
    return d;
}
__device__ __forceinline__ float2 unpack2(u64 v) {
    float2 f; asm("mov.b64 {%0, %1}, %2;" : "=f"(f.x), "=f"(f.y) : "l"(v)); return f;
}

// ---------------------------------------------------------------------------
__global__ void split_kernel(const float* __restrict__ in,
                             fp16* __restrict__ hi, fp16* __restrict__ lo,
                             int n4)
{
    int i = blockIdx.x * 256 + threadIdx.x;
    if (i >= n4) return;
    float4 v = ((const float4*)in)[i];
    fp16 h0 = __float2half_rn(v.x);
    fp16 h1 = __float2half_rn(v.y);
    fp16 h2 = __float2half_rn(v.z);
    fp16 h3 = __float2half_rn(v.w);
    fp16 l0 = __float2half_rn(v.x - __half2float(h0));
    fp16 l1 = __float2half_rn(v.y - __half2float(h1));
    fp16 l2 = __float2half_rn(v.z - __half2float(h2));
    fp16 l3 = __float2half_rn(v.w - __half2float(h3));
    ((ushort4*)hi)[i] = make_ushort4(__half_as_ushort(h0), __half_as_ushort(h1),
                                     __half_as_ushort(h2), __half_as_ushort(h3));
    ((ushort4*)lo)[i] = make_ushort4(__half_as_ushort(l0), __half_as_ushort(l1),
                                     __half_as_ushort(l2), __half_as_ushort(l3));
}

__global__ void split_transpose_kernel(const float* __restrict__ in,
                                       fp16* __restrict__ outh,
                                       fp16* __restrict__ outl, int R, int C)
{
    __shared__ float t[32][33];
    int c0 = blockIdx.x * 32, r0 = blockIdx.y * 32;
#pragma unroll
    for (int i = threadIdx.y; i < 32; i += 8)
        t[i][threadIdx.x] = in[(size_t)(r0 + i) * C + c0 + threadIdx.x];
    __syncthreads();
#pragma unroll
    for (int i = threadIdx.y; i < 32; i += 8) {
        float v = t[threadIdx.x][i];
        fp16 h = __float2half_rn(v);
        fp16 l = __float2half_rn(v - __half2float(h));
        size_t o = (size_t)(c0 + i) * R + r0 + threadIdx.x;
        outh[o] = h; outl[o] = l;
    }
}

__global__ void bias_gather_kernel(const int* __restrict__ ids,
                                   const float* __restrict__ table,
                                   float* __restrict__ biasmat)
{
    int pos = blockIdx.x * 256 + threadIdx.x;
    int id = ids[pos];
#pragma unroll
    for (int h = 0; h < 12; h++)
        biasmat[h * 65536 + pos] = table[id * 12 + h];
}

// ---------------------------------------------------------------------------
// 2-term split-fp16 GEMM: C = Ah@Bh^T + Al@Bh^T + bias.
// CTA 128x128, 8 warps (2M x 4N, warp tile 64x32), BK=32, 3-stage cp.async,
// 2 CTAs/SM. Parts per stage: Ah, Al, Bh (128 rows x 32 halves, 80B stride).
// ---------------------------------------------------------------------------
#define RSB   80
#define PARTB 10240           // 128 * 80
#define STG   30720           // 3 parts
#define GSM   (3 * STG)       // 92160 B, x2 CTA = 184 KB <= 228 KB

__global__ __launch_bounds__(256, 2) void hgemm_kernel(
    const fp16* __restrict__ Ah, const fp16* __restrict__ Al,
    const fp16* __restrict__ Bh,
    const float* __restrict__ bias, float* __restrict__ C,
    int M, int N, int K)
{
    extern __shared__ char smraw[];
    const uint32_t sbase = smem_u32(smraw);
    const int tid = threadIdx.x;
    const int lane = tid & 31;
    const int wid = tid >> 5;
    const int warp_m = wid & 1;      // 2 warps over M (64 rows each)
    const int warp_n = wid >> 1;     // 4 warps over N (32 cols each)
    const int m0 = blockIdx.y * 128;
    const int n0 = blockIdx.x * 128;

    const fp16* Ah_g = Ah + (size_t)m0 * K;
    const fp16* Al_g = Al + (size_t)m0 * K;
    const fp16* Bh_g = Bh + (size_t)n0 * K;

    const uint32_t a_lane = (uint32_t)(((lane & 7) + ((lane >> 3) & 1) * 8) * RSB
                          + (lane >> 4) * 16 + warp_m * 64 * RSB);
    const uint32_t b_lane = (uint32_t)(((lane & 7) + (lane >> 4) * 8) * RSB
                          + ((lane >> 3) & 1) * 16 + warp_n * 32 * RSB);

    float acc[4][4][4];
#pragma unroll
    for (int i = 0; i < 4; i++)
#pragma unroll
        for (int j = 0; j < 4; j++)
#pragma unroll
            for (int q = 0; q < 4; q++) acc[i][j][q] = 0.f;

    const int nch = K >> 5;          // 24
    const int r_ = tid >> 2, seg_ = tid & 3;

#define LOAD_STAGE(ch) do {                                                    \
        const int k0_ = (ch) << 5;                                             \
        const uint32_t sst = sbase + (uint32_t)((ch) % 3) * STG;               \
        _Pragma("unroll")                                                      \
        for (int it = 0; it < 2; it++) {                                       \
            int row = r_ + it * 64;                                            \
            size_t go = (size_t)row * K + k0_ + seg_ * 8;                      \
            uint32_t so = sst + row * RSB + seg_ * 16;                         \
            cp16(so, Ah_g + go);                                               \
            cp16(so + PARTB, Al_g + go);                                       \
            cp16(so + 2 * PARTB, Bh_g + go);                                   \
        }                                                                      \
        CP_COMMIT();                                                           \
    } while (0)

    LOAD_STAGE(0);
    LOAD_STAGE(1);

    for (int ch = 0; ch < nch; ch++) {
        CP_WAIT1();
        __syncthreads();
        if (ch + 2 < nch) LOAD_STAGE(ch + 2);

        const uint32_t sbuf = sbase + (uint32_t)(ch % 3) * STG;
        const uint32_t sAh = sbuf + a_lane;
        const uint32_t sAl = sbuf + PARTB + a_lane;
        const uint32_t sBh = sbuf + 2 * PARTB + b_lane;

#pragma unroll
        for (int ko = 0; ko < 2; ko++) {
            const uint32_t kb = ko * 32;
            uint32_t bh[2][4];
#pragma unroll
            for (int nt16 = 0; nt16 < 2; nt16++)
                ldsm4(bh[nt16], sBh + nt16 * (16 * RSB) + kb);
#pragma unroll
            for (int mt = 0; mt < 4; mt++) {
                uint32_t ah[4], al[4];
                ldsm4(ah, sAh + mt * (16 * RSB) + kb);
                ldsm4(al, sAl + mt * (16 * RSB) + kb);
#pragma unroll
                for (int nt16 = 0; nt16 < 2; nt16++) {
                    mma_fp16(acc[mt][2 * nt16],     ah, &bh[nt16][0]);
                    mma_fp16(acc[mt][2 * nt16 + 1], ah, &bh[nt16][2]);
                    mma_fp16(acc[mt][2 * nt16],     al, &bh[nt16][0]);
                    mma_fp16(acc[mt][2 * nt16 + 1], al, &bh[nt16][2]);
                }
            }
        }
        __syncthreads();
    }
#undef LOAD_STAGE

    // epilogue
    const int quad = lane >> 2, tq = lane & 3;
#pragma unroll
    for (int mt = 0; mt < 4; mt++) {
        const int r = m0 + warp_m * 64 + mt * 16 + quad;
#pragma unroll
        for (int nt = 0; nt < 4; nt++) {
            const int c = n0 + warp_n * 32 + nt * 8 + tq * 2;
            const float b0 = bias[c], b1 = bias[c + 1];
            float* cp = C + (size_t)r * N + c;
            *(float2*)cp = make_float2(acc[mt][nt][0] + b0, acc[mt][nt][1] + b1);
            *(float2*)(cp + 8 * (size_t)N) =
                make_float2(acc[mt][nt][2] + b0, acc[mt][nt][3] + b1);
        }
    }
}

// ---------------------------------------------------------------------------
// Fused attention — f32x2-packed QK and PV loops (R4 version).
// ---------------------------------------------------------------------------
__global__ __launch_bounds__(256) void attn_kernel(
    const float* __restrict__ qkv, const float* __restrict__ biasmat,
    float* __restrict__ attn_out)
{
    extern __shared__ float sm[];
    const int P = 68;
    float* Qs = sm;
    float* Ks = sm + 64 * P;
    float* Vs = sm + 2 * 64 * P;
    float* Ss = sm + 3 * 64 * P;

    const int qt = blockIdx.x, h = blockIdx.y, b = blockIdx.z;
    const int tid = threadIdx.x;
    const int tyy = tid >> 4, txx = tid & 15;
    const int r0 = tyy << 2;
    const int q0 = qt << 6;

    const size_t RS = 2304;
    const float* qg  = qkv + (size_t)(b * 256 + q0) * RS + h * 64;
    const float* kg0 = qkv + (size_t)(b * 256) * RS + 768 + h * 64;
    const float* vg0 = kg0 + 768;

#pragma unroll
    for (int l = 0; l < 4; l++) {
        int f = tid + (l << 8);
        int i = f >> 4, dd = (f & 15) << 2;
        *(float4*)(Qs + i * P + dd) = *(const float4*)(qg + (size_t)i * RS + dd);
    }

    float m[4], lsum[4];
    u64 o2[4][2];
#pragma unroll
    for (int i = 0; i < 4; i++) {
        m[i] = -1e30f; lsum[i] = 0.f;
        o2[i][0] = 0ULL; o2[i][1] = 0ULL;
    }

    const float* bb = biasmat + (size_t)h * 65536 + (size_t)q0 * 256;

    for (int kt = 0; kt < 4; kt++) {
        __syncthreads();
        const float* kg = kg0 + (size_t)(kt * 64) * RS;
        const float* vg = vg0 + (size_t)(kt * 64) * RS;
#pragma unroll
        for (int l = 0; l < 4; l++) {
            int f = tid + (l << 8);
            int i = f >> 4, dd = (f & 15) << 2;
            *(float4*)(Ks + i * P + dd) = *(const float4*)(kg + (size_t)i * RS + dd);
            *(float4*)(Vs + i * P + dd) = *(const float4*)(vg + (size_t)i * RS + dd);
        }
        __syncthreads();

        u64 s2[4][4];
#pragma unroll
        for (int i = 0; i < 4; i++)
#pragma unroll
            for (int j = 0; j < 4; j++) s2[i][j] = 0ULL;

#pragma unroll
        for (int d4 = 0; d4 < 16; d4++) {
            ulonglong2 a[4], kv[4];
#pragma unroll
            for (int i = 0; i < 4; i++)
                a[i] = *(const ulonglong2*)(Qs + (r0 + i) * P + (d4 << 2));
#pragma unroll
            for (int j = 0; j < 4; j++)
                kv[j] = *(const ulonglong2*)(Ks + (txx + (j << 4)) * P + (d4 << 2));
#pragma unroll
            for (int i = 0; i < 4; i++)
#pragma unroll
                for (int j = 0; j < 4; j++)
                    s2[i][j] = fma2(a[i].y, kv[j].y, fma2(a[i].x, kv[j].x, s2[i][j]));
        }

        float s[4][4];
#pragma unroll
        for (int i = 0; i < 4; i++)
#pragma unroll
            for (int j = 0; j < 4; j++) {
                float2 v = unpack2(s2[i][j]);
                s[i][j] = v.x + v.y;
            }

#pragma unroll
        for (int i = 0; i < 4; i++) {
            float tm = -1e30f;
#pragma unroll
            for (int j = 0; j < 4; j++) {
                float bv = bb[(r0 + i) * 256 + kt * 64 + txx + (j << 4)];
                s[i][j] = fmaf(s[i][j], 0.125f, bv);
                tm = fmaxf(tm, s[i][j]);
            }
            tm = fmaxf(tm, __shfl_xor_sync(0xffffffffu, tm, 1));
            tm = fmaxf(tm, __shfl_xor_sync(0xffffffffu, tm, 2));
            tm = fmaxf(tm, __shfl_xor_sync(0xffffffffu, tm, 4));
            tm = fmaxf(tm, __shfl_xor_sync(0xffffffffu, tm, 8));
            float mn = fmaxf(m[i], tm);
            float corr = __expf(m[i] - mn);
            m[i] = mn;
            float ps = 0.f;
#pragma unroll
            for (int j = 0; j < 4; j++) {
                s[i][j] = __expf(s[i][j] - mn);
                ps += s[i][j];
            }
            ps += __shfl_xor_sync(0xffffffffu, ps, 1);
            ps += __shfl_xor_sync(0xffffffffu, ps, 2);
            ps += __shfl_xor_sync(0xffffffffu, ps, 4);
            ps += __shfl_xor_sync(0xffffffffu, ps, 8);
            lsum[i] = lsum[i] * corr + ps;
            u64 c2 = pack2(corr, corr);
            o2[i][0] = mul2(o2[i][0], c2);
            o2[i][1] = mul2(o2[i][1], c2);
        }

#pragma unroll
        for (int j = 0; j < 4; j++)
#pragma unroll
            for (int i = 0; i < 4; i++)
                Ss[(txx + (j << 4)) * P + r0 + i] = s[i][j];
        __syncthreads();

#pragma unroll 8
        for (int k = 0; k < 64; k++) {
            float4 pv = *(const float4*)(Ss + k * P + r0);
            ulonglong2 vv = *(const ulonglong2*)(Vs + k * P + (txx << 2));
            u64 p;
            p = pack2(pv.x, pv.x);
            o2[0][0] = fma2(p, vv.x, o2[0][0]); o2[0][1] = fma2(p, vv.y, o2[0][1]);
            p = pack2(pv.y, pv.y);
            o2[1][0] = fma2(p, vv.x, o2[1][0]); o2[1][1] = fma2(p, vv.y, o2[1][1]);
            p = pack2(pv.z, pv.z);
            o2[2][0] = fma2(p, vv.x, o2[2][0]); o2[2][1] = fma2(p, vv.y, o2[2][1]);
            p = pack2(pv.w, pv.w);
            o2[3][0] = fma2(p, vv.x, o2[3][0]); o2[3][1] = fma2(p, vv.y, o2[3][1]);
        }
    }

    float* og = attn_out + (size_t)(b * 256 + q0) * 768 + h * 64 + (txx << 2);
#pragma unroll
    for (int i = 0; i < 4; i++) {
        float inv = 1.0f / lsum[i];
        float2 v0 = unpack2(o2[i][0]);
        float2 v1 = unpack2(o2[i][1]);
        float4 w = make_float4(v0.x * inv, v0.y * inv, v1.x * inv, v1.y * inv);
        *(float4*)(og + (size_t)(r0 + i) * 768) = w;
    }
}

// ---------------------------------------------------------------------------
extern "C" void kernel_launch(void* const* d_in, const int* in_sizes, int n_in,
                              void* d_out, int out_size)
{
    const float* x     = (const float*)d_in[0];
    const float* Wqkv  = (const float*)d_in[1];
    const float* bqkv  = (const float*)d_in[2];
    const float* Wout  = (const float*)d_in[3];
    const float* bout  = (const float*)d_in[4];
    const float* table = (const float*)d_in[5];
    const int*   ids   = (const int*)d_in[6];
    float* out = (float*)d_out;

    float *qkv, *attn, *bias;
    fp16 *ah, *al, *bqh, *bql, *boh, *bol;
    cudaGetSymbolAddress((void**)&qkv,  g_qkv);
    cudaGetSymbolAddress((void**)&attn, g_attn);
    cudaGetSymbolAddress((void**)&bias, g_bias);
    cudaGetSymbolAddress((void**)&ah,   g_ah);
    cudaGetSymbolAddress((void**)&al,   g_al);
    cudaGetSymbolAddress((void**)&bqh,  g_bqh);
    cudaGetSymbolAddress((void**)&bql,  g_bql);
    cudaGetSymbolAddress((void**)&boh,  g_boh);
    cudaGetSymbolAddress((void**)&bol,  g_bol);

    const int ATTN_SMEM = 4 * 64 * 68 * 4;
    cudaFuncSetAttribute(attn_kernel,
                         cudaFuncAttributeMaxDynamicSharedMemorySize, ATTN_SMEM);
    cudaFuncSetAttribute(hgemm_kernel,
                         cudaFuncAttributeMaxDynamicSharedMemorySize, GSM);

    split_transpose_kernel<<<dim3(2304 / 32, 768 / 32), dim3(32, 8)>>>(
        Wqkv, bqh, bql, 768, 2304);
    split_transpose_kernel<<<dim3(768 / 32, 768 / 32), dim3(32, 8)>>>(
        Wout, boh, bol, 768, 768);
    bias_gather_kernel<<<256, 256>>>(ids, table, bias);
    split_kernel<<<25165824 / 4 / 256, 256>>>(x, ah, al, 25165824 / 4);

    hgemm_kernel<<<dim3(2304 / 128, 32768 / 128), 256, GSM>>>(
        ah, al, bqh, bqkv, qkv, 32768, 2304, 768);

    attn_kernel<<<dim3(4, 12, 128), 256, ATTN_SMEM>>>(qkv, bias, attn);

    split_kernel<<<25165824 / 4 / 256, 256>>>(attn, ah, al, 25165824 / 4);

    hgemm_kernel<<<dim3(768 / 128, 32768 / 128), 256, GSM>>>(
        ah, al, boh, bout, out, 32768, 768, 768);
}